// round 5
// baseline (speedup 1.0000x reference)
#include <cuda_runtime.h>
#include <math.h>

#define BB   8
#define NN   1024
#define KK   32
#define DD   256
#define HH   8
#define DHH  32
#define TD   16
#define NBB  32
#define HIDD 128
#define SHDD 9

// ---------------- scratch (device globals; no allocations allowed) ----------------
__device__ int   g_knn [BB*NN*KK];
__device__ float g_rbf [BB*NN*KK*NBB];       // rbf * cut, per edge
__device__ float g_cut [BB*NN*KK];
__device__ float g_sh  [BB*NN*KK*SHDD];
__device__ float g_node[2][BB*NN*DD];        // ping-pong node features
__device__ float g_P1  [BB*NN*HIDD];         // node[:, :128] @ Wk1[48:176]
__device__ float g_P2  [BB*NN*HIDD];         // node[:, :128] @ Wk1[176:304] + bias + t-part
__device__ float g_m   [BB*NN*HIDD*HH];      // m[j][h] = sum_d Wk2[j, h*32+d] * q[h*32+d]
__device__ float g_vsrc[BB*NN*DD];           // node @ Wv[0:256]
__device__ float g_agg [BB*NN*DD];

__device__ __forceinline__ float gelu_t(float x) {
    // matches jax.nn.gelu (approximate=True, tanh form)
    float x3 = x * x * x;
    return 0.5f * x * (1.f + tanhf(0.7978845608028654f * (x + 0.044715f * x3)));
}

__device__ __forceinline__ unsigned long long umin64(unsigned long long a, unsigned long long b) {
    return a < b ? a : b;
}

// ---------------- kNN: per-node top-32 smallest d2 (self included) ----------------
__global__ void __launch_bounds__(256) k_knn(const float* __restrict__ x) {
    int bn = blockIdx.x;
    int b = bn >> 10, n = bn & 1023;
    const float* pos = x + (size_t)b * NN * 3;
    float px = pos[n*3+0], py = pos[n*3+1], pz = pos[n*3+2];
    int tid = threadIdx.x;
    unsigned long long key[4];
#pragma unroll
    for (int m = 0; m < 4; m++) {
        int j = tid + m * 256;
        float dx = px - pos[j*3+0];
        float dy = py - pos[j*3+1];
        float dz = pz - pos[j*3+2];
        float d2 = dx*dx + dy*dy + dz*dz;   // >= 0 -> float bits are order-preserving
        key[m] = ((unsigned long long)__float_as_uint(d2) << 32) | (unsigned int)j;
    }
    __shared__ unsigned long long s_w[8];
    __shared__ unsigned long long s_best;
    int lane = tid & 31, wp = tid >> 5;
    for (int it = 0; it < KK; it++) {
        unsigned long long bm = umin64(umin64(key[0], key[1]), umin64(key[2], key[3]));
#pragma unroll
        for (int off = 16; off > 0; off >>= 1)
            bm = umin64(bm, __shfl_xor_sync(0xffffffffu, bm, off));
        if (lane == 0) s_w[wp] = bm;
        __syncthreads();
        if (tid == 0) {
            unsigned long long bb = s_w[0];
#pragma unroll
            for (int w = 1; w < 8; w++) bb = umin64(bb, s_w[w]);
            s_best = bb;
            g_knn[(size_t)bn * KK + it] = (int)(bb & 0xffffffffULL);
        }
        __syncthreads();
        unsigned long long bb = s_best;
#pragma unroll
        for (int m = 0; m < 4; m++)
            if (key[m] == bb) key[m] = 0xffffffffffffffffULL;
    }
}

// ---------------- per-edge geometry: sh, cut, rbf*cut ----------------
__global__ void __launch_bounds__(256) k_edges(const float* __restrict__ x) {
    int e = blockIdx.x * 256 + threadIdx.x;          // < BB*NN*KK = 262144
    int b  = e >> 15;                                 // NN*KK = 32768
    int nk = e & 32767;
    int n  = nk >> 5;
    int src = g_knn[e];
    const float* pos = x + (size_t)b * NN * 3;
    float vx = pos[n*3+0] - pos[src*3+0];
    float vy = pos[n*3+1] - pos[src*3+1];
    float vz = pos[n*3+2] - pos[src*3+2];
    float r = sqrtf(vx*vx + vy*vy + vz*vz);
    float inv = 1.f / fmaxf(r, 1e-9f);
    float ux = vx*inv, uy = vy*inv, uz = vz*inv;
    const float S3  = 1.7320508075688772f;
    const float S15 = 3.872983346207417f;
    const float S5  = 2.23606797749979f;
    float sh[9];
    sh[0] = 1.f;
    sh[1] = S3 * ux; sh[2] = S3 * uy; sh[3] = S3 * uz;
    sh[4] = S15 * ux * uy;
    sh[5] = S15 * uy * uz;
    sh[6] = 0.5f * S5 * (3.f * uz * uz - 1.f);
    sh[7] = S15 * ux * uz;
    sh[8] = 0.5f * S15 * (ux*ux - uy*uy);
#pragma unroll
    for (int s = 0; s < 9; s++) g_sh[(size_t)e * SHDD + s] = sh[s];
    float xx = 10.f * (1.f - 0.5f * r);
    float cut = (xx > 0.f) ? 1.4f * expf(-1.f / xx) : 0.f;
    g_cut[e] = cut;
    const float step = 2.0f / 31.0f;
    const float fact = 4.7982245866230005f;   // sqrt(32)*0.95/1.12
    float fc = fact * cut;
    float rs = r / step;
#pragma unroll
    for (int i = 0; i < NBB; i++) {
        float d = rs - (float)i;
        g_rbf[(size_t)e * NBB + i] = expf(-d*d) * fc;
    }
}

// ---------------- node embedding: [y, t] @ W_embed ----------------
__global__ void __launch_bounds__(256) k_embed(const float* __restrict__ y,
                                               const float* __restrict__ t,
                                               const float* __restrict__ W) {
    __shared__ float s_in[19];
    int bn = blockIdx.x, b = bn >> 10, tid = threadIdx.x;
    if (tid < 3) s_in[tid] = y[(size_t)bn * 3 + tid];
    else if (tid < 19) s_in[tid] = t[b * TD + tid - 3];
    __syncthreads();
    float acc = 0.f;
#pragma unroll
    for (int i = 0; i < 19; i++) acc += s_in[i] * W[i * DD + tid];
    g_node[0][(size_t)bn * DD + tid] = acc;
}

// ---------------- per-layer precompute: q->m, vsrc, P1, P2 (16-node tiles) ----------------
__global__ void __launch_bounds__(256) k_pre(int cur,
        const float* __restrict__ Wq, const float* __restrict__ Wv,
        const float* __restrict__ Wk1, const float* __restrict__ Wk2,
        const float* __restrict__ bk1, const float* __restrict__ t) {
    __shared__ float s_nd[16 * DD];
    __shared__ float s_q [16 * DD];
    int tid = threadIdx.x;
    int node0 = blockIdx.x * 16;
    int b = node0 >> 10;
    const float* nodein = g_node[cur];
    const float* np = nodein + (size_t)node0 * DD;
    for (int i = tid; i < 16 * DD; i += 256) s_nd[i] = np[i];
    __syncthreads();

    // q and vsrc (column tid)
    {
        float accq[16], accv[16];
#pragma unroll
        for (int g = 0; g < 16; g++) { accq[g] = 0.f; accv[g] = 0.f; }
        for (int i = 0; i < DD; i += 4) {
            float q0 = Wq[(i+0)*DD + tid], q1 = Wq[(i+1)*DD + tid];
            float q2 = Wq[(i+2)*DD + tid], q3 = Wq[(i+3)*DD + tid];
            float v0 = Wv[(i+0)*DD + tid], v1 = Wv[(i+1)*DD + tid];
            float v2 = Wv[(i+2)*DD + tid], v3 = Wv[(i+3)*DD + tid];
#pragma unroll
            for (int g = 0; g < 16; g++) {
                float4 a = *(const float4*)&s_nd[g*DD + i];
                accq[g] += a.x*q0 + a.y*q1 + a.z*q2 + a.w*q3;
                accv[g] += a.x*v0 + a.y*v1 + a.z*v2 + a.w*v3;
            }
        }
#pragma unroll
        for (int g = 0; g < 16; g++) {
            s_q[g*DD + tid] = accq[g];
            g_vsrc[(size_t)(node0 + g) * DD + tid] = accv[g];
        }
    }

    // P1 (threads 0..127) / P2 (threads 128..255)
    {
        float acc[16];
#pragma unroll
        for (int g = 0; g < 16; g++) acc[g] = 0.f;
        int j = tid & 127;
        int rowbase = (tid < 128) ? 48 : 176;
        const float* W = Wk1 + rowbase * HIDD + j;
        for (int i = 0; i < 128; i += 4) {
            float w0 = W[(i+0)*HIDD], w1 = W[(i+1)*HIDD];
            float w2 = W[(i+2)*HIDD], w3 = W[(i+3)*HIDD];
#pragma unroll
            for (int g = 0; g < 16; g++) {
                float4 a = *(const float4*)&s_nd[g*DD + i];
                acc[g] += a.x*w0 + a.y*w1 + a.z*w2 + a.w*w3;
            }
        }
        if (tid < 128) {
#pragma unroll
            for (int g = 0; g < 16; g++)
                g_P1[(size_t)(node0 + g) * HIDD + j] = acc[g];
        } else {
            float base = bk1[j];
#pragma unroll
            for (int ii = 0; ii < TD; ii++)
                base += t[b * TD + ii] * Wk1[(NBB + ii) * HIDD + j];
#pragma unroll
            for (int g = 0; g < 16; g++)
                g_P2[(size_t)(node0 + g) * HIDD + j] = acc[g] + base;
        }
    }
    __syncthreads();

    // m[j][hh] = sum_d Wk2[j, hh*32+d] * q[hh*32+d]
    {
        int j  = tid & 127;
        int hb = (tid >> 7) * 4;
        for (int hh = hb; hh < hb + 4; hh++) {
            const float* W = Wk2 + j * DD + hh * DHH;
            float4 w[8];
#pragma unroll
            for (int d8 = 0; d8 < 8; d8++) w[d8] = *(const float4*)&W[d8 * 4];
#pragma unroll
            for (int g = 0; g < 16; g++) {
                float s = 0.f;
#pragma unroll
                for (int d8 = 0; d8 < 8; d8++) {
                    float4 q = *(const float4*)&s_q[g*DD + hh*DHH + d8*4];
                    s += w[d8].x*q.x + w[d8].y*q.y + w[d8].z*q.z + w[d8].w*q.w;
                }
                g_m[((size_t)(node0 + g) * HIDD + j) * HH + hh] = s;
            }
        }
    }
}

// ---------------- fused per-node attention (static smem, <48KB) ----------------
__global__ void __launch_bounds__(256) k_attn(const float* __restrict__ Wk1l,
                                              const float* __restrict__ Wvl) {
    // s_h aliases s_wrbf: Wk1 rbf-block is fully consumed before h is written
    __shared__ float s_wrbf [4096];   // Wk1[0:32][0:128]; later reused as h[32][128]
    __shared__ float s_p1   [4096];
    __shared__ float s_m    [1024];
    __shared__ float s_rbf  [1024];
    __shared__ float s_logit[256];
    __shared__ float s_alpha[256];
    __shared__ float s_sh   [288];
    __shared__ float s_p2   [128];
    __shared__ float s_zsh  [72];
    __shared__ float s_cut  [32];
    __shared__ int   s_src  [32];
    float* s_h = s_wrbf;

    int bn = blockIdx.x;
    int b  = bn >> 10;
    int tid = threadIdx.x;
    size_t ebase = (size_t)bn * KK;

    for (int i = tid; i < 4096; i += 256) s_wrbf[i] = Wk1l[i];
    for (int i = tid; i < 1024; i += 256) s_m[i]   = g_m[(size_t)bn * 1024 + i];
    for (int i = tid; i < 1024; i += 256) s_rbf[i] = g_rbf[ebase * NBB + i];
    for (int i = tid; i < 288;  i += 256) s_sh[i]  = g_sh[ebase * SHDD + i];
    if (tid < 32)  { s_cut[tid] = g_cut[ebase + tid]; s_src[tid] = g_knn[ebase + tid]; }
    if (tid < 128) s_p2[tid] = g_P2[(size_t)bn * HIDD + tid];
    __syncthreads();
    for (int i = tid; i < 4096; i += 256) {
        int k = i >> 7, j = i & 127;
        s_p1[i] = g_P1[((size_t)(b * NN) + s_src[k]) * HIDD + j];
    }
    __syncthreads();

    int wp = tid >> 5, lane = tid & 31;
    // h[k][j] = gelu(rbf@Wrbf + P1[src] + P2')  ; warp wp -> k in [4wp,4wp+4), lane -> 4 j's
    {
        float acc[4][4];
#pragma unroll
        for (int a = 0; a < 4; a++)
#pragma unroll
            for (int c = 0; c < 4; c++) acc[a][c] = 0.f;
        int jb = lane * 4;
#pragma unroll
        for (int i = 0; i < NBB; i += 4) {
            float4 w0 = *(const float4*)&s_wrbf[(i+0)*128 + jb];
            float4 w1 = *(const float4*)&s_wrbf[(i+1)*128 + jb];
            float4 w2 = *(const float4*)&s_wrbf[(i+2)*128 + jb];
            float4 w3 = *(const float4*)&s_wrbf[(i+3)*128 + jb];
#pragma unroll
            for (int kk = 0; kk < 4; kk++) {
                float4 rb = *(const float4*)&s_rbf[(wp*4 + kk)*NBB + i];
                acc[kk][0] += rb.x*w0.x + rb.y*w1.x + rb.z*w2.x + rb.w*w3.x;
                acc[kk][1] += rb.x*w0.y + rb.y*w1.y + rb.z*w2.y + rb.w*w3.y;
                acc[kk][2] += rb.x*w0.z + rb.y*w1.z + rb.z*w2.z + rb.w*w3.z;
                acc[kk][3] += rb.x*w0.w + rb.y*w1.w + rb.z*w2.w + rb.w*w3.w;
            }
        }
        __syncthreads();   // all warps done reading s_wrbf before aliased h write
        float4 p2 = *(const float4*)&s_p2[jb];
#pragma unroll
        for (int kk = 0; kk < 4; kk++) {
            int k = wp*4 + kk;
            float4 p1 = *(const float4*)&s_p1[k*128 + jb];
            float4 o;
            o.x = gelu_t(acc[kk][0] + p1.x + p2.x);
            o.y = gelu_t(acc[kk][1] + p1.y + p2.y);
            o.z = gelu_t(acc[kk][2] + p1.z + p2.z);
            o.w = gelu_t(acc[kk][3] + p1.w + p2.w);
            *(float4*)&s_h[k*128 + jb] = o;
        }
    }
    __syncthreads();

    // logits[k][hh] = (h[k] . m[:,hh]) / sqrt(32)
    {
        int k = tid >> 3, hh = tid & 7;
        float s = 0.f;
#pragma unroll 8
        for (int j = 0; j < 128; j += 4) {
            float4 hv = *(const float4*)&s_h[k*128 + j];
            s += hv.x * s_m[(j+0)*8 + hh] + hv.y * s_m[(j+1)*8 + hh]
               + hv.z * s_m[(j+2)*8 + hh] + hv.w * s_m[(j+3)*8 + hh];
        }
        s_logit[tid] = s * 0.17677669529663687f;
    }
    __syncthreads();

    // cutoff-weighted softmax over k (8 threads, one per head)
    if (tid < 8) {
        int hh = tid;
        float mx = -1e30f;
        for (int k = 0; k < KK; k++) mx = fmaxf(mx, s_logit[k*8 + hh]);
        float sum = 0.f;
        for (int k = 0; k < KK; k++) {
            float w = s_cut[k] * expf(s_logit[k*8 + hh] - mx);
            s_alpha[k*8 + hh] = w;
            sum += w;
        }
        float invs = 1.f / (sum + 1e-9f);
        for (int k = 0; k < KK; k++) s_alpha[k*8 + hh] *= invs;
    }
    __syncthreads();

    // zsh[hh][s] = sum_k alpha * sh
    if (tid < 72) {
        int hh = tid / 9, s = tid - hh * 9;
        float acc = 0.f;
        for (int k = 0; k < KK; k++) acc += s_alpha[k*8 + hh] * s_sh[k*9 + s];
        s_zsh[tid] = acc;
    }
    __syncthreads();

    // agg[c] = sum_k alpha*vsrc[src] + sum_s zsh*Wv[256+s]
    {
        int c = tid, hh = tid >> 5;
        const float* vb = g_vsrc + (size_t)(b * NN) * DD;
        float a0 = 0.f, a1 = 0.f, a2 = 0.f, a3 = 0.f;
#pragma unroll
        for (int k = 0; k < KK; k += 4) {
            a0 += s_alpha[(k+0)*8 + hh] * __ldg(&vb[(size_t)s_src[k+0]*DD + c]);
            a1 += s_alpha[(k+1)*8 + hh] * __ldg(&vb[(size_t)s_src[k+1]*DD + c]);
            a2 += s_alpha[(k+2)*8 + hh] * __ldg(&vb[(size_t)s_src[k+2]*DD + c]);
            a3 += s_alpha[(k+3)*8 + hh] * __ldg(&vb[(size_t)s_src[k+3]*DD + c]);
        }
        float acc = (a0 + a1) + (a2 + a3);
#pragma unroll
        for (int s = 0; s < SHDD; s++)
            acc += s_zsh[hh*9 + s] * Wvl[(256 + s)*DD + c];
        g_agg[(size_t)bn * DD + c] = acc;
    }
}

// ---------------- output projection + scalar activation (layers 0..2) ----------------
__global__ void __launch_bounds__(256) k_proj(int cur, const float* __restrict__ Wo) {
    __shared__ float s_agg[16 * DD];
    int tid = threadIdx.x;
    int node0 = blockIdx.x * 16;
    const float* nodein = g_node[cur];
    float* nodeout = g_node[cur ^ 1];
    const float* ap = g_agg + (size_t)node0 * DD;
    for (int i = tid; i < 16 * DD; i += 256) s_agg[i] = ap[i];
    __syncthreads();
    float acc[16];
#pragma unroll
    for (int g = 0; g < 16; g++) acc[g] = 0.f;
    for (int i = 0; i < DD; i += 4) {
        float w0 = Wo[(i+0)*DD + tid], w1 = Wo[(i+1)*DD + tid];
        float w2 = Wo[(i+2)*DD + tid], w3 = Wo[(i+3)*DD + tid];
#pragma unroll
        for (int g = 0; g < 16; g++) {
            float4 a = *(const float4*)&s_agg[g*DD + i];
            acc[g] += a.x*w0 + a.y*w1 + a.z*w2 + a.w*w3;
        }
    }
#pragma unroll
    for (int g = 0; g < 16; g++) {
        float v = nodein[(size_t)(node0 + g) * DD + tid] + acc[g];
        if (tid < 64)       v = gelu_t(v);
        else if (tid < 128) v = tanhf(v);
        nodeout[(size_t)(node0 + g) * DD + tid] = v;
    }
}

// ---------------- final projection agg @ Wo_out -> [B,N,3] ----------------
__global__ void __launch_bounds__(256) k_final(const float* __restrict__ Wo_out,
                                               float* __restrict__ out) {
    int gid = blockIdx.x * 256 + threadIdx.x;
    if (gid >= BB * NN * 3) return;
    int n = gid / 3, c = gid - n * 3;
    const float* ap = g_agg + (size_t)n * DD;
    float acc = 0.f;
#pragma unroll 4
    for (int i = 0; i < DD; i++) acc += ap[i] * Wo_out[i * 3 + c];
    out[gid] = acc;
}

// ---------------- launch ----------------
extern "C" void kernel_launch(void* const* d_in, const int* in_sizes, int n_in,
                              void* d_out, int out_size) {
    const float* x       = (const float*)d_in[0];
    const float* y       = (const float*)d_in[1];
    const float* t       = (const float*)d_in[2];
    const float* W_embed = (const float*)d_in[3];
    const float* Wk1     = (const float*)d_in[4];
    const float* bk1     = (const float*)d_in[5];
    const float* Wk2     = (const float*)d_in[6];
    const float* Wq      = (const float*)d_in[7];
    const float* Wv      = (const float*)d_in[8];
    const float* Wo      = (const float*)d_in[9];
    const float* Wo_out  = (const float*)d_in[10];
    float* out = (float*)d_out;

    k_knn  <<<BB*NN, 256>>>(x);
    k_edges<<<BB*NN*KK/256, 256>>>(x);
    k_embed<<<BB*NN, 256>>>(y, t, W_embed);

    for (int l = 0; l < 4; l++) {
        int cur = l & 1;
        const float* Wk1l = Wk1 + (size_t)l * 304 * HIDD;
        const float* Wvl  = Wv  + (size_t)l * 265 * DD;
        k_pre<<<BB*NN/16, 256>>>(cur,
                                 Wq + (size_t)l * DD * DD,
                                 Wvl, Wk1l,
                                 Wk2 + (size_t)l * HIDD * DD,
                                 bk1 + (size_t)l * HIDD,
                                 t);
        k_attn<<<BB*NN, 256>>>(Wk1l, Wvl);
        if (l < 3) k_proj<<<BB*NN/16, 256>>>(cur, Wo + (size_t)l * DD * DD);
    }
    k_final<<<(BB*NN*3 + 255)/256, 256>>>(Wo_out, out);
}